// round 10
// baseline (speedup 1.0000x reference)
#include <cuda_runtime.h>
#include <cuda_bf16.h>

#define NG 2048
#define HW 128
#define TANFOV 0.5f
#define NEARP 0.2f
#define AMIN (1.0f/255.0f)
#define LOG2E 1.4426950408889634f
#define TEPS 1e-7f
#define CHUNKS 8              // z-buckets: z in [2 + 0.5k, 2 + 0.5(k+1))
#define NCTA 512              // 64 tiles x 8 buckets
#define KCAP 256

// preprocessed per-gaussian data, indexed by ORIGINAL index
__device__ float4 g_c[NG];    // px, py, cullR2, z      (cull record)
__device__ float4 g_a[NG];    // px, py, ca2, cb2
__device__ float4 g_bb[NG];   // cc2, op, colR, colG
__device__ float  g_cbl[NG];  // colB
// per-bucket partial (r,g,b,T) per pixel
__device__ float4 g_part[CHUNKS][HW*HW];
// monotonic sync state (graph-replay safe)
__device__ unsigned g_count;
__device__ unsigned g_phase;
__device__ unsigned g_tile_cnt[64];

__device__ __forceinline__ float fast_exp2(float x) {
    float r;
    asm("ex2.approx.f32 %0, %1;" : "=f"(r) : "f"(x));
    return r;
}

__global__ void __launch_bounds__(256, 4) fused_kernel(
        const float* __restrict__ means3D,
        const float* __restrict__ colors,
        const float* __restrict__ opacities,
        const float* __restrict__ cov3Ds,
        const float* __restrict__ bg,
        float* __restrict__ out_img,
        float* __restrict__ out_radii) {
    __shared__ unsigned long long s_keys[KCAP];   // 2KB
    __shared__ float4 s_A[KCAP];                  // 4KB
    __shared__ float4 s_B[KCAP];                  // 4KB
    __shared__ float  s_Cb[KCAP];                 // 1KB
    __shared__ int    s_wcnt[8];
    __shared__ int    s_n;
    __shared__ unsigned s_ph, s_last;

    int t = threadIdx.x;
    int bx = blockIdx.x;
    int w = t >> 5, lane = t & 31;

    float bg0 = __ldg(&bg[0]), bg1 = __ldg(&bg[1]), bg2 = __ldg(&bg[2]);

    if (t == 0) s_ph = *(volatile unsigned*)&g_phase;
    __syncthreads();
    unsigned myphase = s_ph;

    // ===== Phase 1: preprocess 4 gaussians per CTA (threads 0-3) =====
    if (t < 4) {
        int i = bx * 4 + t;
        const float fx = HW / (2.0f * TANFOV);
        const float fy = fx;

        float x = __ldg(&means3D[3*i + 0]);
        float y = __ldg(&means3D[3*i + 1]);
        float z = __ldg(&means3D[3*i + 2]);
        float invz = 1.0f / z;

        float px = fx * x * invz + 0.5f * HW;
        float py = fy * y * invz + 0.5f * HW;

        const float lim = 1.3f * TANFOV;
        float txn = fminf(fmaxf(x * invz, -lim), lim) * z;
        float tyn = fminf(fmaxf(y * invz, -lim), lim) * z;

        float xx = __ldg(&cov3Ds[6*i+0]), xy = __ldg(&cov3Ds[6*i+1]);
        float xz = __ldg(&cov3Ds[6*i+2]), yy = __ldg(&cov3Ds[6*i+3]);
        float yz = __ldg(&cov3Ds[6*i+4]), zz = __ldg(&cov3Ds[6*i+5]);

        float j00 = fx * invz;
        float j02 = -fx * txn * invz * invz;
        float j11 = fy * invz;
        float j12 = -fy * tyn * invz * invz;

        float M00 = j00*xx + j02*xz;
        float M01 = j00*xy + j02*yz;
        float M02 = j00*xz + j02*zz;
        float M11 = j11*yy + j12*yz;
        float M12 = j11*yz + j12*zz;

        float a = M00*j00 + M02*j02 + 0.3f;
        float b = M01*j11 + M02*j12;
        float c = M11*j11 + M12*j12 + 0.3f;

        float det = a*c - b*b;
        float invdet = 1.0f / det;
        float conA = c * invdet;
        float conB = -b * invdet;
        float conC = a * invdet;

        float mid = 0.5f * (a + c);
        float lam1 = mid + sqrtf(fmaxf(0.1f, mid*mid - det));

        bool valid = (z > NEARP) && (det > 0.0f);
        float radii = valid ? ceilf(3.0f * sqrtf(lam1)) : 0.0f;

        float op = __ldg(&opacities[i]);
        float cullR2;
        if (!valid) cullR2 = -1.0f;
        else {
            float tt = op * 255.0f;
            cullR2 = (tt <= 1.0f) ? -1.0f : 2.0f * lam1 * logf(tt);
        }

        out_radii[i] = radii;
        g_c[i]   = make_float4(px, py, cullR2, z);
        g_a[i]   = make_float4(px, py, -0.5f*LOG2E*conA, -LOG2E*conB);
        g_bb[i]  = make_float4(-0.5f*LOG2E*conC, op,
                               __ldg(&colors[3*i+0]), __ldg(&colors[3*i+1]));
        g_cbl[i] = __ldg(&colors[3*i+2]);
    }

    // ===== grid barrier (512 CTAs; residency via launch_bounds(256,4)) =====
    __syncthreads();
    if (t == 0) {
        __threadfence();
        unsigned old = atomicAdd(&g_count, 1u);
        if (old == NCTA - 1) {
            g_count = 0;
            __threadfence();
            atomicAdd(&g_phase, 1u);
        } else {
            while (*(volatile unsigned*)&g_phase == myphase) __nanosleep(20);
        }
        __threadfence();
    }
    __syncthreads();

    // ===== Phase 2: (tile, z-bucket) cull -> compact -> sort -> blend =====
    int tile   = bx & 63;
    int bucket = bx >> 6;
    int tx0 = (tile & 7) * 16;
    int ty0 = (tile >> 3) * 16;
    float X = (float)(tx0 + (t & 15));
    float Y = (float)(ty0 + (t >> 4));
    float rx0 = (float)tx0, rx1 = (float)(tx0 + 15);
    float ry0 = (float)ty0, ry1 = (float)(ty0 + 15);

    // cull all 2048: bucket match AND rect-distance test (8 per thread)
    unsigned keepmask = 0u;
    int cnt = 0;
    #pragma unroll
    for (int k = 0; k < 8; k++) {
        int g = (k << 8) | t;
        float4 cu = g_c[g];
        int b = (int)((cu.w - 2.0f) * 2.0f);
        b = (b < 0) ? 0 : ((b > 7) ? 7 : b);
        float ddx = fmaxf(0.0f, fmaxf(rx0 - cu.x, cu.x - rx1));
        float ddy = fmaxf(0.0f, fmaxf(ry0 - cu.y, cu.y - ry1));
        bool keep = (b == bucket) && ((ddx*ddx + ddy*ddy) <= cu.z);
        keepmask |= (unsigned)keep << k;
        cnt += keep;
    }

    // CTA exclusive scan of per-thread counts
    int inc = cnt;
    #pragma unroll
    for (int d = 1; d < 32; d <<= 1) {
        int v = __shfl_up_sync(0xffffffffu, inc, d);
        if (lane >= d) inc += v;
    }
    if (lane == 31) s_wcnt[w] = inc;
    __syncthreads();
    int base = inc - cnt;
    int total = 0;
    #pragma unroll
    for (int ww = 0; ww < 8; ww++) {
        int cn = s_wcnt[ww];
        base  += (ww < w) ? cn : 0;
        total += cn;
    }
    if (t == 0) s_n = (total < KCAP) ? total : KCAP;

    // write keys (zbits<<32 | original idx)
    int pos = base;
    #pragma unroll
    for (int k = 0; k < 8; k++) {
        if ((keepmask >> k) & 1u) {
            int g = (k << 8) | t;
            float zv = g_c[g].w;               // L1 hit
            if (pos < KCAP)
                s_keys[pos] = ((unsigned long long)__float_as_uint(zv) << 32)
                              | (unsigned)g;
            pos++;
        }
    }
    __syncthreads();
    int n = s_n;

    float T = 1.0f, accr = 0.0f, accg = 0.0f, accb = 0.0f;

    if (n > 0) {
        if (n > 1) {
            int npad = 1;
            while (npad < n) npad <<= 1;
            for (int i = n + t; i < npad; i += 256)
                s_keys[i] = 0xFFFFFFFFFFFFFFFFull;
            __syncthreads();

            // bitonic ascending (z, then idx) == stable argsort order
            for (int k = 2; k <= npad; k <<= 1) {
                for (int j = k >> 1; j > 0; j >>= 1) {
                    for (int i = t; i < npad; i += 256) {
                        int l = i ^ j;
                        if (l > i) {
                            unsigned long long va = s_keys[i];
                            unsigned long long vb = s_keys[l];
                            bool up = ((i & k) == 0);
                            if (up ? (va > vb) : (va < vb)) {
                                s_keys[i] = vb;
                                s_keys[l] = va;
                            }
                        }
                    }
                    __syncthreads();
                }
            }
        }

        // gather survivors in sorted order
        for (int i = t; i < n; i += 256) {
            int gi = (int)(s_keys[i] & 0xFFFFFFFFu);
            s_A[i]  = g_a[gi];
            s_B[i]  = g_bb[gi];
            s_Cb[i] = g_cbl[gi];
        }
        __syncthreads();

        // blend front-to-back
        for (int j = 0; j < n; j++) {
            if ((j & 3) == 0 &&
                __ballot_sync(0xffffffffu, T >= TEPS) == 0u) break;
            float4 a  = s_A[j];
            float4 b4 = s_B[j];
            float cb  = s_Cb[j];
            float dx = a.x - X;
            float dy = a.y - Y;
            float p2 = a.z*dx*dx + a.w*dx*dy + b4.x*dy*dy;  // power * log2e
            float e = fast_exp2(p2);
            float alpha = fminf(b4.y * e, 0.99f);
            if (p2 > 0.0f || alpha < AMIN) alpha = 0.0f;
            float wgt = alpha * T;
            accr = fmaf(wgt, b4.z, accr);
            accg = fmaf(wgt, b4.w, accg);
            accb = fmaf(wgt, cb,   accb);
            T = fmaf(-alpha, T, T);
        }
    }

    int p = (ty0 + (t >> 4)) * HW + tx0 + (t & 15);
    g_part[bucket][p] = make_float4(accr, accg, accb, T);

    // last arriving bucket-CTA of this tile folds the partials
    __syncthreads();
    if (t == 0) {
        __threadfence();
        unsigned old = atomicAdd(&g_tile_cnt[tile], 1u);
        s_last = ((old & (CHUNKS-1u)) == CHUNKS-1u) ? 1u : 0u;
    }
    __syncthreads();

    if (s_last) {
        __threadfence();   // acquire: all partials visible
        float Tc = 1.0f, r = 0.0f, g = 0.0f, b = 0.0f;
        #pragma unroll
        for (int k = 0; k < CHUNKS; k++) {
            float4 c;
            if (k == bucket) c = make_float4(accr, accg, accb, T);
            else             c = __ldcg(&g_part[k][p]);
            r = fmaf(Tc, c.x, r);
            g = fmaf(Tc, c.y, g);
            b = fmaf(Tc, c.z, b);
            Tc *= c.w;
        }
        out_img[p]           = fmaf(Tc, bg0, r);
        out_img[HW*HW + p]   = fmaf(Tc, bg1, g);
        out_img[2*HW*HW + p] = fmaf(Tc, bg2, b);
    }
}

extern "C" void kernel_launch(void* const* d_in, const int* in_sizes, int n_in,
                              void* d_out, int out_size) {
    const float* means3D   = (const float*)d_in[0];
    const float* colors    = (const float*)d_in[1];
    const float* opacities = (const float*)d_in[2];
    const float* cov3Ds    = (const float*)d_in[3];
    const float* bg        = (const float*)d_in[4];
    float* out = (float*)d_out;
    float* out_img   = out;              // 3*128*128
    float* out_radii = out + 3*HW*HW;    // 2048

    fused_kernel<<<NCTA, 256>>>(means3D, colors, opacities, cov3Ds, bg,
                                out_img, out_radii);
}

// round 11
// speedup vs baseline: 1.1641x; 1.1641x over previous
#include <cuda_runtime.h>
#include <cuda_bf16.h>

#define NG 2048
#define HW 128
#define TANFOV 0.5f
#define NEARP 0.2f
#define AMIN (1.0f/255.0f)
#define LOG2E 1.4426950408889634f
#define CHUNKS 8              // z-buckets: z in [2+0.5k, 2+0.5(k+1))
#define NCTA 512              // 64 tiles x 8 buckets
#define BCAP 512              // bucket capacity (mean 256)
#define SCAP 128              // per-(tile,bucket) survivor capacity (mean ~18)

// per-gaussian blend data, indexed by ORIGINAL index
__device__ float4 g_a[NG];    // px, py, ca2, cb2
__device__ float4 g_bb[NG];   // cc2, op, colR, colG
__device__ float  g_cbl[NG];  // colB
// z-bucketed cull records
__device__ float4 g_bc[CHUNKS][BCAP];  // px, py, cullR2, z
__device__ int    g_bi[CHUNKS][BCAP];  // original index
__device__ unsigned g_bcnt[CHUNKS];    // reset to 0 at end of each run
// per-bucket partial (r,g,b,T) per pixel
__device__ float4 g_part[CHUNKS][HW*HW];
// monotonic sync state (graph-replay safe)
__device__ unsigned g_count;
__device__ unsigned g_phase;
__device__ unsigned g_tile_cnt[64];
__device__ unsigned g_done;

__device__ __forceinline__ float fast_exp2(float x) {
    float r;
    asm("ex2.approx.f32 %0, %1;" : "=f"(r) : "f"(x));
    return r;
}

__global__ void __launch_bounds__(256, 4) fused_kernel(
        const float* __restrict__ means3D,
        const float* __restrict__ colors,
        const float* __restrict__ opacities,
        const float* __restrict__ cov3Ds,
        const float* __restrict__ bg,
        float* __restrict__ out_img,
        float* __restrict__ out_radii) {
    __shared__ unsigned long long s_keys[SCAP];   // 1KB
    __shared__ int    s_ord[SCAP];                // 0.5KB
    __shared__ float4 s_A[SCAP];                  // 2KB
    __shared__ float4 s_B[SCAP];                  // 2KB
    __shared__ float  s_Cb[SCAP];                 // 0.5KB
    __shared__ int    s_wcnt[8];
    __shared__ int    s_n;
    __shared__ unsigned s_ph, s_last;

    int t = threadIdx.x;
    int bx = blockIdx.x;
    int w = t >> 5, lane = t & 31;

    float bg0 = __ldg(&bg[0]), bg1 = __ldg(&bg[1]), bg2 = __ldg(&bg[2]);

    if (t == 0) s_ph = *(volatile unsigned*)&g_phase;
    __syncthreads();
    unsigned myphase = s_ph;

    // ===== Phase 1: preprocess 4 gaussians per CTA (threads 0-3); no sort =====
    if (t < 4) {
        int i = bx * 4 + t;
        const float fx = HW / (2.0f * TANFOV);
        const float fy = fx;

        float x = __ldg(&means3D[3*i + 0]);
        float y = __ldg(&means3D[3*i + 1]);
        float z = __ldg(&means3D[3*i + 2]);
        float invz = 1.0f / z;

        float px = fx * x * invz + 0.5f * HW;
        float py = fy * y * invz + 0.5f * HW;

        const float lim = 1.3f * TANFOV;
        float txn = fminf(fmaxf(x * invz, -lim), lim) * z;
        float tyn = fminf(fmaxf(y * invz, -lim), lim) * z;

        float xx = __ldg(&cov3Ds[6*i+0]), xy = __ldg(&cov3Ds[6*i+1]);
        float xz = __ldg(&cov3Ds[6*i+2]), yy = __ldg(&cov3Ds[6*i+3]);
        float yz = __ldg(&cov3Ds[6*i+4]), zz = __ldg(&cov3Ds[6*i+5]);

        float j00 = fx * invz;
        float j02 = -fx * txn * invz * invz;
        float j11 = fy * invz;
        float j12 = -fy * tyn * invz * invz;

        float M00 = j00*xx + j02*xz;
        float M01 = j00*xy + j02*yz;
        float M02 = j00*xz + j02*zz;
        float M11 = j11*yy + j12*yz;
        float M12 = j11*yz + j12*zz;

        float a = M00*j00 + M02*j02 + 0.3f;
        float b = M01*j11 + M02*j12;
        float c = M11*j11 + M12*j12 + 0.3f;

        float det = a*c - b*b;
        float invdet = 1.0f / det;
        float conA = c * invdet;
        float conB = -b * invdet;
        float conC = a * invdet;

        float mid = 0.5f * (a + c);
        float lam1 = mid + sqrtf(fmaxf(0.1f, mid*mid - det));

        bool valid = (z > NEARP) && (det > 0.0f);
        float radii = valid ? ceilf(3.0f * sqrtf(lam1)) : 0.0f;
        out_radii[i] = radii;

        float op = __ldg(&opacities[i]);
        float cullR2 = -1.0f;
        if (valid) {
            float tt = op * 255.0f;
            if (tt > 1.0f) cullR2 = 2.0f * lam1 * logf(tt);
        }

        g_a[i]   = make_float4(px, py, -0.5f*LOG2E*conA, -LOG2E*conB);
        g_bb[i]  = make_float4(-0.5f*LOG2E*conC, op,
                               __ldg(&colors[3*i+0]), __ldg(&colors[3*i+1]));
        g_cbl[i] = __ldg(&colors[3*i+2]);

        if (cullR2 >= 0.0f) {   // only potentially-visible gaussians enter buckets
            int bkt = (int)((z - 2.0f) * 2.0f);
            bkt = (bkt < 0) ? 0 : ((bkt > 7) ? 7 : bkt);
            unsigned slot = atomicAdd(&g_bcnt[bkt], 1u);
            if (slot < BCAP) {
                g_bc[bkt][slot] = make_float4(px, py, cullR2, z);
                g_bi[bkt][slot] = i;
            }
        }
    }

    // ===== grid barrier (512 CTAs; residency via launch_bounds(256,4)) =====
    __syncthreads();
    if (t == 0) {
        __threadfence();
        unsigned old = atomicAdd(&g_count, 1u);
        if (old == NCTA - 1) {
            g_count = 0;
            __threadfence();
            atomicAdd(&g_phase, 1u);
        } else {
            while (*(volatile unsigned*)&g_phase == myphase) __nanosleep(20);
        }
        __threadfence();
    }
    __syncthreads();

    // ===== Phase 2: (tile, bucket) cull -> compact -> rank-sort -> blend =====
    int tile   = bx & 63;
    int bucket = bx >> 6;
    int tx0 = (tile & 7) * 16;
    int ty0 = (tile >> 3) * 16;
    float X = (float)(tx0 + (t & 15));
    float Y = (float)(ty0 + (t >> 4));
    float rx0 = (float)tx0, rx1 = (float)(tx0 + 15);
    float ry0 = (float)ty0, ry1 = (float)(ty0 + 15);

    int bcnt = (int)__ldcg(&g_bcnt[bucket]);
    if (bcnt > BCAP) bcnt = BCAP;

    // cull up to 512 bucket entries (2 per thread), coalesced
    bool k0 = false, k1 = false;
    float z0 = 0.0f, z1 = 0.0f;
    int id0 = 0, id1 = 0;
    if (t < bcnt) {
        float4 cu = g_bc[bucket][t];
        float ddx = fmaxf(0.0f, fmaxf(rx0 - cu.x, cu.x - rx1));
        float ddy = fmaxf(0.0f, fmaxf(ry0 - cu.y, cu.y - ry1));
        k0 = (ddx*ddx + ddy*ddy) <= cu.z;
        z0 = cu.w; id0 = g_bi[bucket][t];
    }
    int t2 = t + 256;
    if (t2 < bcnt) {
        float4 cu = g_bc[bucket][t2];
        float ddx = fmaxf(0.0f, fmaxf(rx0 - cu.x, cu.x - rx1));
        float ddy = fmaxf(0.0f, fmaxf(ry0 - cu.y, cu.y - ry1));
        k1 = (ddx*ddx + ddy*ddy) <= cu.z;
        z1 = cu.w; id1 = g_bi[bucket][t2];
    }
    int cc = (int)k0 + (int)k1;

    // CTA exclusive scan
    int inc = cc;
    #pragma unroll
    for (int d = 1; d < 32; d <<= 1) {
        int v = __shfl_up_sync(0xffffffffu, inc, d);
        if (lane >= d) inc += v;
    }
    if (lane == 31) s_wcnt[w] = inc;
    __syncthreads();
    int base = inc - cc;
    int total = 0;
    #pragma unroll
    for (int ww = 0; ww < 8; ww++) {
        int cn = s_wcnt[ww];
        base  += (ww < w) ? cn : 0;
        total += cn;
    }
    if (t == 0) s_n = (total < SCAP) ? total : SCAP;

    int pos = base;
    if (k0) {
        if (pos < SCAP)
            s_keys[pos] = ((unsigned long long)__float_as_uint(z0) << 32) | (unsigned)id0;
        pos++;
    }
    if (k1) {
        if (pos < SCAP)
            s_keys[pos] = ((unsigned long long)__float_as_uint(z1) << 32) | (unsigned)id1;
        pos++;
    }
    __syncthreads();

    int n = s_n;

    // rank-sort survivors: key = (zbits, idx) ascending == stable argsort order
    if (t < n) {
        unsigned long long ki = s_keys[t];
        int rnk = 0;
        for (int j = 0; j < n; j++)
            rnk += (s_keys[j] < ki);
        s_ord[rnk] = (int)(ki & 0xFFFFFFFFu);
    }
    __syncthreads();

    // gather survivor blend data in sorted order
    if (t < n) {
        int gi = s_ord[t];
        s_A[t]  = g_a[gi];
        s_B[t]  = g_bb[gi];
        s_Cb[t] = g_cbl[gi];
    }
    __syncthreads();

    // blend front-to-back
    float T = 1.0f, accr = 0.0f, accg = 0.0f, accb = 0.0f;
    for (int j = 0; j < n; j++) {
        float4 a  = s_A[j];
        float4 b4 = s_B[j];
        float cb  = s_Cb[j];
        float dx = a.x - X;
        float dy = a.y - Y;
        float p2 = a.z*dx*dx + a.w*dx*dy + b4.x*dy*dy;  // power * log2(e)
        float e = fast_exp2(p2);
        float alpha = fminf(b4.y * e, 0.99f);
        if (p2 > 0.0f || alpha < AMIN) alpha = 0.0f;
        float wgt = alpha * T;
        accr = fmaf(wgt, b4.z, accr);
        accg = fmaf(wgt, b4.w, accg);
        accb = fmaf(wgt, cb,   accb);
        T = fmaf(-alpha, T, T);
    }

    int p = (ty0 + (t >> 4)) * HW + tx0 + (t & 15);
    g_part[bucket][p] = make_float4(accr, accg, accb, T);

    // last arriving bucket-CTA of this tile folds the partials
    __syncthreads();
    if (t == 0) {
        __threadfence();
        unsigned old = atomicAdd(&g_tile_cnt[tile], 1u);
        s_last = ((old & (CHUNKS-1u)) == CHUNKS-1u) ? 1u : 0u;
    }
    __syncthreads();

    if (s_last) {
        __threadfence();   // acquire: all partials visible
        float Tc = 1.0f, r = 0.0f, g = 0.0f, b = 0.0f;
        #pragma unroll
        for (int k = 0; k < CHUNKS; k++) {
            float4 c;
            if (k == bucket) c = make_float4(accr, accg, accb, T);
            else             c = __ldcg(&g_part[k][p]);
            r = fmaf(Tc, c.x, r);
            g = fmaf(Tc, c.y, g);
            b = fmaf(Tc, c.z, b);
            Tc *= c.w;
        }
        out_img[p]           = fmaf(Tc, bg0, r);
        out_img[HW*HW + p]   = fmaf(Tc, bg1, g);
        out_img[2*HW*HW + p] = fmaf(Tc, bg2, b);
    }

    // run end: the provably-last CTA resets bucket counters for the next replay
    if (t == 0) {
        __threadfence();
        unsigned old = atomicAdd(&g_done, 1u);
        if ((old & (NCTA-1u)) == NCTA-1u) {
            #pragma unroll
            for (int k = 0; k < CHUNKS; k++) g_bcnt[k] = 0u;
        }
    }
}

extern "C" void kernel_launch(void* const* d_in, const int* in_sizes, int n_in,
                              void* d_out, int out_size) {
    const float* means3D   = (const float*)d_in[0];
    const float* colors    = (const float*)d_in[1];
    const float* opacities = (const float*)d_in[2];
    const float* cov3Ds    = (const float*)d_in[3];
    const float* bg        = (const float*)d_in[4];
    float* out = (float*)d_out;
    float* out_img   = out;              // 3*128*128
    float* out_radii = out + 3*HW*HW;    // 2048

    fused_kernel<<<NCTA, 256>>>(means3D, colors, opacities, cov3Ds, bg,
                                out_img, out_radii);
}